// round 5
// baseline (speedup 1.0000x reference)
#include <cuda_runtime.h>

// ---------------------------------------------------------------------------
// Problem constants
// ---------------------------------------------------------------------------
#define Bn      1024
#define Tt      34
#define E       128
#define TWO_E   256
#define L0N     (Bn*Tt*8)    // 278528
#define L1N     (Bn*Tt*4)    // 139264
#define L2N     (Bn*Tt*2)    // 69632
#define L3N     (Bn*Tt)      // 34816
#define LFN     (Bn*9)       // 9216
#define LBASE0  0
#define LBASE1  (LBASE0 + 4*L0N)
#define LBASE2  (LBASE1 + 4*L1N)
#define LBASE3  (LBASE2 + 4*L2N)
#define LBASE4  (LBASE3 + 4*L3N)
#define LTOTAL  (LBASE4 + 3*LFN)

// ---- nf kernel geometry: 64 rows/block, 8x8 thread tile --------------------
#define TMNF    64
#define XS1     68            // padded row stride for Xt/Ht (floats), 64+4

#define NF_XT_OFF   0
#define NF_HT_OFF   69632                  // 256*68*4
#define NF_WS_OFF   (69632 + 69632)
#define NF_SN_OFF   (NF_WS_OFF + 32768)
#define NF_SMEM     (NF_SN_OFF + 256)      // 172288

// ---- lf kernel geometry (unchanged): 32 rows/block, 4x8 tile ---------------
#define TMLF    32
#define XSTR    36

#define LF_XT_OFF   0
#define LF_HT_OFF   36864
#define LF_WS_OFF   (36864 + 73728)
#define LF_SN_OFF   (LF_WS_OFF + 32768)
#define LF_SMEM     (LF_SN_OFF + 128)

typedef unsigned long long ull;

// ---------------------------------------------------------------------------
// Packed fp32x2 helpers (sm_103a). Bit-exact: each half is an IEEE fused fmaf.
// ---------------------------------------------------------------------------
__device__ __forceinline__ void fma2(ull& d, ull a, ull b) {
    asm("fma.rn.f32x2 %0, %1, %2, %0;" : "+l"(d) : "l"(a), "l"(b));
}
__device__ __forceinline__ ull pack_dup(float w) {
    ull r; unsigned wi = __float_as_uint(w);
    asm("mov.b64 %0, {%1, %2};" : "=l"(r) : "r"(wi), "r"(wi));
    return r;
}
__device__ __forceinline__ float2 unpack2(ull v) {
    unsigned lo, hi;
    asm("mov.b64 {%0, %1}, %2;" : "=r"(lo), "=r"(hi) : "l"(v));
    float2 f; f.x = __uint_as_float(lo); f.y = __uint_as_float(hi);
    return f;
}

// ---------------------------------------------------------------------------
// Scratch (device globals; no allocation allowed)
// ---------------------------------------------------------------------------
__device__ float g_buf0[(size_t)L0N * E];
__device__ float g_buf1[(size_t)L1N * E];
__device__ float g_roots[(size_t)L3N * E];
__device__ float g_stmt[(size_t)LFN * E];
__device__ int   g_counts[20];
__device__ int   g_lists[LTOTAL];

__global__ void zero_counts_kernel() {
    if (threadIdx.x < 20) g_counts[threadIdx.x] = 0;
}

// ---------------------------------------------------------------------------
// Expert compaction (warp-aggregated atomics). Grid exact multiple of 256.
// ---------------------------------------------------------------------------
__global__ void compact_kernel(const int* __restrict__ nf_ids,
                               const int* __restrict__ lf_ids) {
    int gid = blockIdx.x * 256 + threadIdx.x;
    int slot, store_base, nid;
    if (gid < L0N) {
        nid = gid;
        int bt = nid >> 3, j = nid & 7;
        int id = nf_ids[bt * 15 + j];
        slot = id;               store_base = LBASE0 + id * L0N;
    } else if (gid < L0N + L1N) {
        nid = gid - L0N;
        int bt = nid >> 2, j = nid & 3;
        int id = nf_ids[bt * 15 + 8 + j];
        slot = 4 + id;           store_base = LBASE1 + id * L1N;
    } else if (gid < L0N + L1N + L2N) {
        nid = gid - (L0N + L1N);
        int bt = nid >> 1, j = nid & 1;
        int id = nf_ids[bt * 15 + 12 + j];
        slot = 8 + id;           store_base = LBASE2 + id * L2N;
    } else if (gid < L0N + L1N + L2N + L3N) {
        nid = gid - (L0N + L1N + L2N);
        int id = nf_ids[nid * 15 + 14];
        slot = 12 + id;          store_base = LBASE3 + id * L3N;
    } else {
        nid = gid - (L0N + L1N + L2N + L3N);
        int id = lf_ids[nid];
        slot = 16 + id;          store_base = LBASE4 + id * LFN;
    }
    unsigned mm = __match_any_sync(0xFFFFFFFFu, slot);
    int lane   = threadIdx.x & 31;
    int leader = __ffs(mm) - 1;
    int rank   = __popc(mm & ((1u << lane) - 1));
    int base   = 0;
    if (lane == leader) base = atomicAdd(&g_counts[slot], __popc(mm));
    base = __shfl_sync(0xFFFFFFFFu, base, leader);
    g_lists[store_base + base + rank] = nid;
}

// ---------------------------------------------------------------------------
// nf expert MLP: 256 -> relu(256) -> 128.
// 64-row block, 8x8 thread tile, packed f32x2 FMAs. 0.5 LDS-bytes/FLOP.
// ---------------------------------------------------------------------------
__global__ void __launch_bounds__(256, 1)
nf_gemm_kernel(int lvl,
               const int* __restrict__ leaf_idx,
               const float* __restrict__ ent_emb,
               const float* __restrict__ W1, const float* __restrict__ b1,
               const float* __restrict__ W2, const float* __restrict__ b2) {
    extern __shared__ char smem[];
    float* Xt = (float*)(smem + NF_XT_OFF);       // [256][68]
    float* Ht = (float*)(smem + NF_HT_OFF);       // [256][68]
    float* Ws = (float*)(smem + NF_WS_OFF);       // [32][256] / [32][128]
    int* s_node = (int*)(smem + NF_SN_OFF);

    int stride, list_base, counts_off;
    const float* in; float* outp;
    switch (lvl) {
        case 0:  stride = L0N; list_base = LBASE0; counts_off = 0;  in = 0;      outp = g_buf0;  break;
        case 1:  stride = L1N; list_base = LBASE1; counts_off = 4;  in = g_buf0; outp = g_buf1;  break;
        case 2:  stride = L2N; list_base = LBASE2; counts_off = 8;  in = g_buf1; outp = g_buf0;  break;
        default: stride = L3N; list_base = LBASE3; counts_off = 12; in = g_buf0; outp = g_roots; break;
    }

    int k_ex  = blockIdx.y;
    int count = g_counts[counts_off + k_ex];
    int m0    = blockIdx.x * TMNF;
    if (m0 >= count) return;
    int mrows = min(TMNF, count - m0);
    int tid   = threadIdx.x;

    if (tid < TMNF)
        s_node[tid] = (tid < mrows) ? g_lists[list_base + k_ex * stride + m0 + tid] : -1;
    __syncthreads();

    // ---- stage X transposed: X_t[k][m]. Warp w rows 8w..8w+7; lane = k%32 --
    {
        int wid = tid >> 5, lane = tid & 31;
        #pragma unroll
        for (int i = 0; i < 8; i++) {
            int m = wid * 8 + i;
            int node = s_node[m];
            if (lvl == 0) {
                int l0 = 0, l1 = 0;
                if (node >= 0) { l0 = leaf_idx[node * 2]; l1 = leaf_idx[node * 2 + 1]; }
                #pragma unroll
                for (int j = 0; j < 8; j++) {
                    int k = lane + 32 * j;
                    float v = 0.f;
                    if (node >= 0)
                        v = (k < E) ? ent_emb[(size_t)l0 * E + k]
                                    : ent_emb[(size_t)l1 * E + (k - E)];
                    Xt[k * XS1 + m] = v;
                }
            } else {
                const float* src = (node >= 0) ? (in + (size_t)node * TWO_E) : 0;
                #pragma unroll
                for (int j = 0; j < 8; j++) {
                    int k = lane + 32 * j;
                    Xt[k * XS1 + m] = src ? src[k] : 0.f;
                }
            }
        }
    }

    // ---- GEMM1: 64x256 = X(64x256) @ W1(256x256), k-chunks of 32 ----------
    int rg = tid & 7,  cg = tid >> 3;      // 8 row-groups x 32 col-groups
    int r0 = rg * 8,   c0 = cg * 8;
    const float* W1k = W1 + (size_t)k_ex * TWO_E * TWO_E;
    ull acc[8][4];                          // [row][colpair]
    #pragma unroll
    for (int i = 0; i < 8; i++)
        #pragma unroll
        for (int j = 0; j < 4; j++) acc[i][j] = 0ull;

    float4 pre[8];
    {
        const float4* src = (const float4*)W1k;
        #pragma unroll
        for (int i = 0; i < 8; i++) pre[i] = __ldg(&src[tid + i * 256]);
    }
    for (int cb = 0; cb < 8; cb++) {
        float4* Wsv = (float4*)Ws;
        #pragma unroll
        for (int i = 0; i < 8; i++) Wsv[tid + i * 256] = pre[i];
        __syncthreads();
        if (cb < 7) {
            const float4* src = (const float4*)(W1k + (cb + 1) * 32 * TWO_E);
            #pragma unroll
            for (int i = 0; i < 8; i++) pre[i] = __ldg(&src[tid + i * 256]);
        }
        #pragma unroll
        for (int kk = 0; kk < 32; kk++) {
            const float* xrow = &Xt[(cb * 32 + kk) * XS1 + r0];
            float4 xa = *(const float4*)xrow;
            float4 xb = *(const float4*)(xrow + 4);
            ulonglong2 wa = *(const ulonglong2*)&Ws[kk * 256 + c0];
            ulonglong2 wb = *(const ulonglong2*)&Ws[kk * 256 + c0 + 4];
            ull xd[8] = {pack_dup(xa.x), pack_dup(xa.y), pack_dup(xa.z), pack_dup(xa.w),
                         pack_dup(xb.x), pack_dup(xb.y), pack_dup(xb.z), pack_dup(xb.w)};
            #pragma unroll
            for (int i = 0; i < 8; i++) {
                fma2(acc[i][0], xd[i], wa.x);
                fma2(acc[i][1], xd[i], wa.y);
                fma2(acc[i][2], xd[i], wb.x);
                fma2(acc[i][3], xd[i], wb.y);
            }
        }
        __syncthreads();
    }

    // ---- bias + relu -> H_t[c][m] ------------------------------------------
    {
        float4 bva = __ldg((const float4*)(b1 + k_ex * TWO_E + c0));
        float4 bvb = __ldg((const float4*)(b1 + k_ex * TWO_E + c0 + 4));
        float bv[8] = {bva.x, bva.y, bva.z, bva.w, bvb.x, bvb.y, bvb.z, bvb.w};
        float a[8][8];
        #pragma unroll
        for (int i = 0; i < 8; i++)
            #pragma unroll
            for (int jp = 0; jp < 4; jp++) {
                float2 p = unpack2(acc[i][jp]);
                a[i][2 * jp]     = p.x;
                a[i][2 * jp + 1] = p.y;
            }
        #pragma unroll
        for (int j = 0; j < 8; j++) {
            float4 h0, h1;
            h0.x = fmaxf(a[0][j] + bv[j], 0.f);
            h0.y = fmaxf(a[1][j] + bv[j], 0.f);
            h0.z = fmaxf(a[2][j] + bv[j], 0.f);
            h0.w = fmaxf(a[3][j] + bv[j], 0.f);
            h1.x = fmaxf(a[4][j] + bv[j], 0.f);
            h1.y = fmaxf(a[5][j] + bv[j], 0.f);
            h1.z = fmaxf(a[6][j] + bv[j], 0.f);
            h1.w = fmaxf(a[7][j] + bv[j], 0.f);
            *(float4*)&Ht[(c0 + j) * XS1 + r0]     = h0;
            *(float4*)&Ht[(c0 + j) * XS1 + r0 + 4] = h1;
        }
    }
    __syncthreads();

    // ---- GEMM2: 64x128 = H(64x256) @ W2(256x128), k-chunks of 32 -----------
    int rg2 = tid & 15, cg2 = tid >> 4;    // 16 row-groups x 16 col-groups
    int r0b = rg2 * 4,  c2 = cg2 * 8;
    ull a2[4][4];
    #pragma unroll
    for (int i = 0; i < 4; i++)
        #pragma unroll
        for (int j = 0; j < 4; j++) a2[i][j] = 0ull;

    const float* W2k = W2 + (size_t)k_ex * TWO_E * E;
    float4 p2[4];
    {
        const float4* src = (const float4*)W2k;
        #pragma unroll
        for (int i = 0; i < 4; i++) p2[i] = __ldg(&src[tid + i * 256]);
    }
    for (int cb = 0; cb < 8; cb++) {
        float4* Wsv = (float4*)Ws;
        #pragma unroll
        for (int i = 0; i < 4; i++) Wsv[tid + i * 256] = p2[i];
        __syncthreads();
        if (cb < 7) {
            const float4* src = (const float4*)(W2k + (cb + 1) * 32 * E);
            #pragma unroll
            for (int i = 0; i < 4; i++) p2[i] = __ldg(&src[tid + i * 256]);
        }
        #pragma unroll
        for (int kk = 0; kk < 32; kk++) {
            float4 h = *(const float4*)&Ht[(cb * 32 + kk) * XS1 + r0b];
            ulonglong2 wa = *(const ulonglong2*)&Ws[kk * E + c2];
            ulonglong2 wb = *(const ulonglong2*)&Ws[kk * E + c2 + 4];
            ull hd[4] = {pack_dup(h.x), pack_dup(h.y), pack_dup(h.z), pack_dup(h.w)};
            #pragma unroll
            for (int i = 0; i < 4; i++) {
                fma2(a2[i][0], hd[i], wa.x);
                fma2(a2[i][1], hd[i], wa.y);
                fma2(a2[i][2], hd[i], wb.x);
                fma2(a2[i][3], hd[i], wb.y);
            }
        }
        __syncthreads();
    }

    // ---- bias2 + store ------------------------------------------------------
    {
        float4 bva = __ldg((const float4*)(b2 + k_ex * E + c2));
        float4 bvb = __ldg((const float4*)(b2 + k_ex * E + c2 + 4));
        #pragma unroll
        for (int i = 0; i < 4; i++) {
            int node = s_node[r0b + i];
            if (node >= 0) {
                float2 p0 = unpack2(a2[i][0]);
                float2 p1 = unpack2(a2[i][1]);
                float2 p2u = unpack2(a2[i][2]);
                float2 p3 = unpack2(a2[i][3]);
                float4 o0, o1;
                o0.x = p0.x + bva.x; o0.y = p0.y + bva.y;
                o0.z = p1.x + bva.z; o0.w = p1.y + bva.w;
                o1.x = p2u.x + bvb.x; o1.y = p2u.y + bvb.y;
                o1.z = p3.x + bvb.z; o1.w = p3.y + bvb.w;
                *(float4*)(outp + (size_t)node * E + c2)     = o0;
                *(float4*)(outp + (size_t)node * E + c2 + 4) = o1;
            }
        }
    }
}

// ---------------------------------------------------------------------------
// lf expert MLP: 256 -> relu(512) -> 128. (unchanged; ~3% of FLOPs)
// ---------------------------------------------------------------------------
__global__ void __launch_bounds__(256, 1)
lf_gemm_kernel(const float* __restrict__ W1, const float* __restrict__ b1,
               const float* __restrict__ W2, const float* __restrict__ b2) {
    extern __shared__ char smem[];
    float* Xt = (float*)(smem + LF_XT_OFF);       // [256][36]
    float* Ht = (float*)(smem + LF_HT_OFF);       // [512][36]
    float* Ws = (float*)(smem + LF_WS_OFF);
    int* s_node = (int*)(smem + LF_SN_OFF);

    int k_ex  = blockIdx.y;
    int count = g_counts[16 + k_ex];
    int m0    = blockIdx.x * TMLF;
    if (m0 >= count) return;
    int mrows = min(TMLF, count - m0);
    int tid   = threadIdx.x;

    if (tid < TMLF)
        s_node[tid] = (tid < mrows) ? g_lists[LBASE4 + k_ex * LFN + m0 + tid] : -1;
    __syncthreads();

    {   // stage X transposed
        int wid = tid >> 5, lane = tid & 31;
        #pragma unroll
        for (int i = 0; i < 4; i++) {
            int m = wid * 4 + i;
            int node = s_node[m];
            const float* src = 0;
            if (node >= 0) {
                int b = node / 9, g = node % 9;
                src = g_roots + ((size_t)b * Tt + 16 + 2 * g) * E;
            }
            #pragma unroll
            for (int j = 0; j < 8; j++) {
                int k = lane + 32 * j;
                Xt[k * XSTR + m] = src ? src[k] : 0.f;
            }
        }
    }

    int rg = tid & 7,  cg = tid >> 3;
    int r0 = rg * 4,   c0 = cg * 8;
    const float* W1k = W1 + (size_t)k_ex * TWO_E * 512;

    for (int pass = 0; pass < 2; pass++) {
        ull acc[4][4];
        #pragma unroll
        for (int i = 0; i < 4; i++)
            #pragma unroll
            for (int j = 0; j < 4; j++) acc[i][j] = 0ull;

        float4 pre[8];
        {
            #pragma unroll
            for (int i = 0; i < 8; i++) {
                int f = tid + i * 256, r = f >> 6, c4 = f & 63;
                pre[i] = __ldg((const float4*)W1k + (size_t)r * 128 + pass * 64 + c4);
            }
        }
        for (int cb = 0; cb < 8; cb++) {
            float4* Wsv = (float4*)Ws;
            #pragma unroll
            for (int i = 0; i < 8; i++) Wsv[tid + i * 256] = pre[i];
            __syncthreads();
            if (cb < 7) {
                #pragma unroll
                for (int i = 0; i < 8; i++) {
                    int f = tid + i * 256, r = f >> 6, c4 = f & 63;
                    pre[i] = __ldg((const float4*)W1k
                                   + (size_t)((cb + 1) * 32 + r) * 128 + pass * 64 + c4);
                }
            }
            #pragma unroll
            for (int kk = 0; kk < 32; kk++) {
                float4 x = *(const float4*)&Xt[(cb * 32 + kk) * XSTR + r0];
                ulonglong2 wa = *(const ulonglong2*)&Ws[kk * 256 + c0];
                ulonglong2 wb = *(const ulonglong2*)&Ws[kk * 256 + c0 + 4];
                ull xd[4] = {pack_dup(x.x), pack_dup(x.y), pack_dup(x.z), pack_dup(x.w)};
                #pragma unroll
                for (int i = 0; i < 4; i++) {
                    fma2(acc[i][0], xd[i], wa.x);
                    fma2(acc[i][1], xd[i], wa.y);
                    fma2(acc[i][2], xd[i], wb.x);
                    fma2(acc[i][3], xd[i], wb.y);
                }
            }
            __syncthreads();
        }
        int cabs = pass * 256 + c0;
        float4 bva = __ldg((const float4*)(b1 + k_ex * 512 + cabs));
        float4 bvb = __ldg((const float4*)(b1 + k_ex * 512 + cabs + 4));
        float bv[8] = {bva.x, bva.y, bva.z, bva.w, bvb.x, bvb.y, bvb.z, bvb.w};
        float a[4][8];
        #pragma unroll
        for (int i = 0; i < 4; i++)
            #pragma unroll
            for (int jp = 0; jp < 4; jp++) {
                float2 p = unpack2(acc[i][jp]);
                a[i][2 * jp]     = p.x;
                a[i][2 * jp + 1] = p.y;
            }
        #pragma unroll
        for (int j = 0; j < 8; j++) {
            float4 h;
            h.x = fmaxf(a[0][j] + bv[j], 0.f);
            h.y = fmaxf(a[1][j] + bv[j], 0.f);
            h.z = fmaxf(a[2][j] + bv[j], 0.f);
            h.w = fmaxf(a[3][j] + bv[j], 0.f);
            *(float4*)&Ht[(cabs + j) * XSTR + r0] = h;
        }
    }
    __syncthreads();

    int c2 = (tid >> 3) * 4;
    ull a2[4][2];
    #pragma unroll
    for (int i = 0; i < 4; i++) { a2[i][0] = 0ull; a2[i][1] = 0ull; }

    const float* W2k = W2 + (size_t)k_ex * 512 * E;
    float4 p2[4];
    {
        const float4* src = (const float4*)W2k;
        #pragma unroll
        for (int i = 0; i < 4; i++) p2[i] = __ldg(&src[tid + i * 256]);
    }
    for (int cb = 0; cb < 16; cb++) {
        float4* Wsv = (float4*)Ws;
        #pragma unroll
        for (int i = 0; i < 4; i++) Wsv[tid + i * 256] = p2[i];
        __syncthreads();
        if (cb < 15) {
            const float4* src = (const float4*)(W2k + (size_t)(cb + 1) * 32 * E);
            #pragma unroll
            for (int i = 0; i < 4; i++) p2[i] = __ldg(&src[tid + i * 256]);
        }
        #pragma unroll
        for (int kk = 0; kk < 32; kk++) {
            float4 h = *(const float4*)&Ht[(cb * 32 + kk) * XSTR + r0];
            ulonglong2 w = *(const ulonglong2*)&Ws[kk * E + c2];
            ull hd[4] = {pack_dup(h.x), pack_dup(h.y), pack_dup(h.z), pack_dup(h.w)};
            #pragma unroll
            for (int i = 0; i < 4; i++) {
                fma2(a2[i][0], hd[i], w.x);
                fma2(a2[i][1], hd[i], w.y);
            }
        }
        __syncthreads();
    }
    {
        float4 bv = __ldg((const float4*)(b2 + k_ex * E + c2));
        #pragma unroll
        for (int i = 0; i < 4; i++) {
            int node = s_node[r0 + i];
            if (node >= 0) {
                float2 pa = unpack2(a2[i][0]);
                float2 pb = unpack2(a2[i][1]);
                float4 o;
                o.x = pa.x + bv.x; o.y = pa.y + bv.y;
                o.z = pb.x + bv.z; o.w = pb.y + bv.w;
                *(float4*)(g_stmt + (size_t)node * E + c2) = o;
            }
        }
    }
}

// ---------------------------------------------------------------------------
// Attention tail (unchanged)
// ---------------------------------------------------------------------------
__global__ void attn_kernel(const int* __restrict__ th_idx,
                            const float* __restrict__ th_emb,
                            const float* __restrict__ he_W, const float* __restrict__ he_b,
                            const float* __restrict__ hg_W, const float* __restrict__ hg_b,
                            const float* __restrict__ ht_W, const float* __restrict__ ht_b,
                            float* __restrict__ out) {
    __shared__ float obj[E];
    __shared__ float q[E];
    __shared__ float keys[16][E + 1];
    __shared__ float a[16];
    int b = blockIdx.x, tid = threadIdx.x;

    float o = g_stmt[((size_t)b * 9 + 8) * E + tid];
    obj[tid] = o;
    out[(size_t)b * 512 + tid] = o;
    __syncthreads();

    for (int t3 = 0; t3 < 3; t3++) {
        int n; const float *W, *bb;
        if (t3 == 0) {
            n = 8; W = hg_W; bb = hg_b;
            for (int i = 0; i < 8; i++)
                keys[i][tid] = g_stmt[((size_t)b * 9 + i) * E + tid];
        } else if (t3 == 1) {
            n = 16; W = he_W; bb = he_b;
            for (int i = 0; i < 16; i++)
                keys[i][tid] = g_roots[((size_t)b * Tt + i) * E + tid];
        } else {
            n = 8; W = ht_W; bb = ht_b;
            for (int i = 0; i < 8; i++)
                keys[i][tid] = th_emb[(size_t)th_idx[b * 8 + i] * E + tid];
        }
        float qv = bb[tid];
        for (int k = 0; k < E; k++) qv = fmaf(obj[k], W[k * E + tid], qv);
        q[tid] = qv;
        __syncthreads();
        if (tid < n) {
            float s = 0.f;
            for (int d = 0; d < E; d++) s = fmaf(keys[tid][d], q[d], s);
            a[tid] = s;
        }
        __syncthreads();
        if (tid == 0) {
            float mx = -1e30f;
            for (int i = 0; i < n; i++) mx = fmaxf(mx, a[i]);
            float sum = 0.f;
            for (int i = 0; i < n; i++) { float e = expf(a[i] - mx); a[i] = e; sum += e; }
            float inv = 1.f / sum;
            for (int i = 0; i < n; i++) a[i] *= inv;
        }
        __syncthreads();
        float c = 0.f;
        for (int i = 0; i < n; i++) c = fmaf(a[i], keys[i][tid], c);
        int off = (t3 == 0) ? 128 : (t3 == 1) ? 256 : 384;
        out[(size_t)b * 512 + off + tid] = c;
        __syncthreads();
    }
}

// ---------------------------------------------------------------------------
extern "C" void kernel_launch(void* const* d_in, const int* in_sizes, int n_in,
                              void* d_out, int out_size) {
    const int*   leaf_idx = (const int*)d_in[0];
    const int*   nf_ids   = (const int*)d_in[1];
    const int*   lf_ids   = (const int*)d_in[2];
    const int*   th_idx   = (const int*)d_in[3];
    const float* ent_emb  = (const float*)d_in[4];
    const float* th_emb   = (const float*)d_in[5];
    const float* nf_W1 = (const float*)d_in[6];
    const float* nf_b1 = (const float*)d_in[7];
    const float* nf_W2 = (const float*)d_in[8];
    const float* nf_b2 = (const float*)d_in[9];
    const float* lf_W1 = (const float*)d_in[10];
    const float* lf_b1 = (const float*)d_in[11];
    const float* lf_W2 = (const float*)d_in[12];
    const float* lf_b2 = (const float*)d_in[13];
    const float* he_W = (const float*)d_in[14];
    const float* he_b = (const float*)d_in[15];
    const float* hg_W = (const float*)d_in[16];
    const float* hg_b = (const float*)d_in[17];
    const float* ht_W = (const float*)d_in[18];
    const float* ht_b = (const float*)d_in[19];
    float* out = (float*)d_out;

    cudaFuncSetAttribute(nf_gemm_kernel, cudaFuncAttributeMaxDynamicSharedMemorySize, NF_SMEM);
    cudaFuncSetAttribute(lf_gemm_kernel, cudaFuncAttributeMaxDynamicSharedMemorySize, LF_SMEM);

    zero_counts_kernel<<<1, 32>>>();
    compact_kernel<<<(L0N + L1N + L2N + L3N + LFN) / 256, 256>>>(nf_ids, lf_ids);

    nf_gemm_kernel<<<dim3(L0N / TMNF, 4), 256, NF_SMEM>>>(0, leaf_idx, ent_emb,
        nf_W1, nf_b1, nf_W2, nf_b2);
    nf_gemm_kernel<<<dim3(L1N / TMNF, 4), 256, NF_SMEM>>>(1, leaf_idx, ent_emb,
        nf_W1, nf_b1, nf_W2, nf_b2);
    nf_gemm_kernel<<<dim3(L2N / TMNF, 4), 256, NF_SMEM>>>(2, leaf_idx, ent_emb,
        nf_W1, nf_b1, nf_W2, nf_b2);
    nf_gemm_kernel<<<dim3(L3N / TMNF, 4), 256, NF_SMEM>>>(3, leaf_idx, ent_emb,
        nf_W1, nf_b1, nf_W2, nf_b2);

    lf_gemm_kernel<<<dim3(LFN / TMLF, 3), 256, LF_SMEM>>>(lf_W1, lf_b1, lf_W2, lf_b2);

    attn_kernel<<<Bn, E>>>(th_idx, th_emb, he_W, he_b, hg_W, hg_b, ht_W, ht_b, out);
}

// round 8
// speedup vs baseline: 1.1898x; 1.1898x over previous
#include <cuda_runtime.h>
#include <cuda_bf16.h>

typedef unsigned long long ull;
typedef unsigned int u32;

// ---------------------------------------------------------------------------
// Problem constants
// ---------------------------------------------------------------------------
#define Bn      1024
#define Tt      34
#define E       128
#define TWO_E   256
#define L0N     (Bn*Tt*8)    // 278528
#define L1N     (Bn*Tt*4)    // 139264
#define L2N     (Bn*Tt*2)    // 69632
#define L3N     (Bn*Tt)      // 34816
#define LFN     (Bn*9)       // 9216
#define LBASE0  0
#define LBASE1  (LBASE0 + 4*L0N)
#define LBASE2  (LBASE1 + 4*L1N)
#define LBASE3  (LBASE2 + 4*L2N)
#define LBASE4  (LBASE3 + 4*L3N)
#define LTOTAL  (LBASE4 + 3*LFN)

// ---- nf HMMA kernel geometry ----------------------------------------------
// M=64 rows/block, 8 warps: wm = wid>>2 (2 M-groups of 32), wn = wid&3.
// GEMM1: N=256 (warp tile 32x64), GEMM2: N=128 (warp tile 32x32). K=256 both.
// A (X then H) in smem bf16 hi/lo, row-major stride 264 bf16 (528B).
// B (W chunk, 32 k) in smem [n][k] bf16, stride 40 bf16 (80B), double-buffered.
#define AS_HI   0
#define AS_LO   33792                  // 64*528
#define BS_O    67584
#define BBUF    40960                  // per buffer: hi 20480 + lo 20480
#define SN_O    (BS_O + 2*BBUF)       // 149504
#define NF_SMEM (SN_O + 256)          // 149760

// ---- lf scalar kernel geometry (unchanged, ~3% of FLOPs) -------------------
#define TMLF    32
#define XSTR    36
#define LF_XT_OFF   0
#define LF_HT_OFF   36864
#define LF_WS_OFF   (36864 + 73728)
#define LF_SN_OFF   (LF_WS_OFF + 32768)
#define LF_SMEM     (LF_SN_OFF + 128)

// ---------------------------------------------------------------------------
// PTX helpers: ldmatrix + mma (baseline PTX, legal at compute_103)
// ---------------------------------------------------------------------------
__device__ __forceinline__ u32 smem_u32(const void* p) {
    u32 a;
    asm("{ .reg .u64 t; cvta.to.shared.u64 t, %1; cvt.u32.u64 %0, t; }"
        : "=r"(a) : "l"(p));
    return a;
}

#define LDMX4(r, addr) \
    asm volatile("ldmatrix.sync.aligned.m8n8.x4.shared.b16 {%0,%1,%2,%3}, [%4];" \
        : "=r"((r)[0]), "=r"((r)[1]), "=r"((r)[2]), "=r"((r)[3]) : "r"(addr))

#define MMA_BF16(d, a, b) \
    asm volatile("mma.sync.aligned.m16n8k16.row.col.f32.bf16.bf16.f32 " \
        "{%0,%1,%2,%3}, {%4,%5,%6,%7}, {%8,%9}, {%0,%1,%2,%3};" \
        : "+f"((d)[0]), "+f"((d)[1]), "+f"((d)[2]), "+f"((d)[3]) \
        : "r"((a)[0]), "r"((a)[1]), "r"((a)[2]), "r"((a)[3]), \
          "r"((b)[0]), "r"((b)[1]))

// split fp32 pair -> packed bf16 hi pair + lo pair (x ~= hi + lo to ~2^-17)
__device__ __forceinline__ void split2(float v0, float v1, u32& hp, u32& lp) {
    __nv_bfloat16 h0 = __float2bfloat16_rn(v0);
    __nv_bfloat16 h1 = __float2bfloat16_rn(v1);
    float r0 = v0 - __bfloat162float(h0);
    float r1 = v1 - __bfloat162float(h1);
    __nv_bfloat16 l0 = __float2bfloat16_rn(r0);
    __nv_bfloat16 l1 = __float2bfloat16_rn(r1);
    hp = (u32)__bfloat16_as_ushort(h0) | ((u32)__bfloat16_as_ushort(h1) << 16);
    lp = (u32)__bfloat16_as_ushort(l0) | ((u32)__bfloat16_as_ushort(l1) << 16);
}

// ---------------------------------------------------------------------------
// Packed fp32x2 helpers (lf scalar kernel)
// ---------------------------------------------------------------------------
__device__ __forceinline__ void fma2(ull& d, ull a, ull b) {
    asm("fma.rn.f32x2 %0, %1, %2, %0;" : "+l"(d) : "l"(a), "l"(b));
}
__device__ __forceinline__ ull pack_dup(float w) {
    ull r; unsigned wi = __float_as_uint(w);
    asm("mov.b64 %0, {%1, %2};" : "=l"(r) : "r"(wi), "r"(wi));
    return r;
}
__device__ __forceinline__ float2 unpack2(ull v) {
    unsigned lo, hi;
    asm("mov.b64 {%0, %1}, %2;" : "=r"(lo), "=r"(hi) : "l"(v));
    float2 f; f.x = __uint_as_float(lo); f.y = __uint_as_float(hi);
    return f;
}

// ---------------------------------------------------------------------------
// Scratch (device globals; no allocation allowed)
// ---------------------------------------------------------------------------
__device__ float g_buf0[(size_t)L0N * E];
__device__ float g_buf1[(size_t)L1N * E];
__device__ float g_roots[(size_t)L3N * E];
__device__ float g_stmt[(size_t)LFN * E];
__device__ int   g_counts[20];
__device__ int   g_lists[LTOTAL];

__global__ void zero_counts_kernel() {
    if (threadIdx.x < 20) g_counts[threadIdx.x] = 0;
}

// ---------------------------------------------------------------------------
// Expert compaction (warp-aggregated atomics)
// ---------------------------------------------------------------------------
__global__ void compact_kernel(const int* __restrict__ nf_ids,
                               const int* __restrict__ lf_ids) {
    int gid = blockIdx.x * 256 + threadIdx.x;
    int slot, store_base, nid;
    if (gid < L0N) {
        nid = gid;
        int bt = nid >> 3, j = nid & 7;
        int id = nf_ids[bt * 15 + j];
        slot = id;               store_base = LBASE0 + id * L0N;
    } else if (gid < L0N + L1N) {
        nid = gid - L0N;
        int bt = nid >> 2, j = nid & 3;
        int id = nf_ids[bt * 15 + 8 + j];
        slot = 4 + id;           store_base = LBASE1 + id * L1N;
    } else if (gid < L0N + L1N + L2N) {
        nid = gid - (L0N + L1N);
        int bt = nid >> 1, j = nid & 1;
        int id = nf_ids[bt * 15 + 12 + j];
        slot = 8 + id;           store_base = LBASE2 + id * L2N;
    } else if (gid < L0N + L1N + L2N + L3N) {
        nid = gid - (L0N + L1N + L2N);
        int id = nf_ids[nid * 15 + 14];
        slot = 12 + id;          store_base = LBASE3 + id * L3N;
    } else {
        nid = gid - (L0N + L1N + L2N + L3N);
        int id = lf_ids[nid];
        slot = 16 + id;          store_base = LBASE4 + id * LFN;
    }
    unsigned mm = __match_any_sync(0xFFFFFFFFu, slot);
    int lane   = threadIdx.x & 31;
    int leader = __ffs(mm) - 1;
    int rank   = __popc(mm & ((1u << lane) - 1));
    int base   = 0;
    if (lane == leader) base = atomicAdd(&g_counts[slot], __popc(mm));
    base = __shfl_sync(0xFFFFFFFFu, base, leader);
    g_lists[store_base + base + rank] = nid;
}

// ---------------------------------------------------------------------------
// nf expert MLP on HMMA (mma.sync bf16, split hi/lo, fp32 accum).
// ---------------------------------------------------------------------------
__global__ void __launch_bounds__(256, 1)
nf_mma_kernel(int lvl,
              const int* __restrict__ leaf_idx,
              const float* __restrict__ ent_emb,
              const float* __restrict__ W1, const float* __restrict__ b1,
              const float* __restrict__ W2, const float* __restrict__ b2) {
    extern __shared__ char smem[];
    u32 sb = smem_u32(smem);
    int tid = threadIdx.x, wid = tid >> 5, lane = tid & 31;
    int wm = wid >> 2, wn = wid & 3;

    int stride, list_base, counts_off;
    const float* in; float* outp;
    switch (lvl) {
        case 0:  stride = L0N; list_base = LBASE0; counts_off = 0;  in = 0;      outp = g_buf0;  break;
        case 1:  stride = L1N; list_base = LBASE1; counts_off = 4;  in = g_buf0; outp = g_buf1;  break;
        case 2:  stride = L2N; list_base = LBASE2; counts_off = 8;  in = g_buf1; outp = g_buf0;  break;
        default: stride = L3N; list_base = LBASE3; counts_off = 12; in = g_buf0; outp = g_roots; break;
    }

    int k_ex  = blockIdx.y;
    int count = g_counts[counts_off + k_ex];
    int m0    = blockIdx.x * 64;
    if (m0 >= count) return;

    int* s_node = (int*)(smem + SN_O);
    if (tid < 64)
        s_node[tid] = (m0 + tid < count) ? g_lists[list_base + k_ex * stride + m0 + tid] : -1;
    __syncthreads();

    const float* W1k = W1 + (size_t)k_ex * TWO_E * TWO_E;
    const float* W2k = W2 + (size_t)k_ex * TWO_E * E;
    const float* b1p = b1 + k_ex * TWO_E;
    const float* b2p = b2 + k_ex * E;

    // ---- stage X -> As hi/lo (64 rows x 256 cols bf16, stride 264) --------
    {
        int m = tid >> 2, q = tid & 3;
        int node = s_node[m];
        for (int i = 0; i < 32; i++) {
            int kp = q * 32 + i;
            int col = 2 * kp;
            float x0 = 0.f, x1 = 0.f;
            if (node >= 0) {
                if (lvl == 0) {
                    int l = (col < E) ? leaf_idx[2 * node] : leaf_idx[2 * node + 1];
                    float2 v = *(const float2*)(ent_emb + (size_t)l * E + (col & (E - 1)));
                    x0 = v.x; x1 = v.y;
                } else {
                    float2 v = *(const float2*)(in + (size_t)node * TWO_E + col);
                    x0 = v.x; x1 = v.y;
                }
            }
            u32 hp, lp; split2(x0, x1, hp, lp);
            *(u32*)(smem + AS_HI + m * 528 + kp * 4) = hp;
            *(u32*)(smem + AS_LO + m * 528 + kp * 4) = lp;
        }
    }

    // W staging helper geometry: lane covers (dn = lane&7 -> n, kpv = lane>>3)
    int dn = lane & 7, kpv = lane >> 3;

    // ---- stage W1 chunk 0 directly ----------------------------------------
    {
        char* buf = smem + BS_O;
        for (int rr = 0; rr < 16; rr++) {
            int g = wid * 16 + rr, nb = g >> 2, kb = g & 3;
            int n = nb * 8 + dn, kp = kb * 4 + kpv;
            float w0 = __ldg(W1k + (size_t)(2 * kp) * TWO_E + n);
            float w1 = __ldg(W1k + (size_t)(2 * kp + 1) * TWO_E + n);
            u32 hp, lp; split2(w0, w1, hp, lp);
            *(u32*)(buf + n * 80 + kp * 4) = hp;
            *(u32*)(buf + 20480 + n * 80 + kp * 4) = lp;
        }
    }
    __syncthreads();

    // =================== GEMM1: C[64,256] = X @ W1 =========================
    float acc[2][8][4];
    #pragma unroll
    for (int mf = 0; mf < 2; mf++)
        #pragma unroll
        for (int nf = 0; nf < 8; nf++)
            #pragma unroll
            for (int j = 0; j < 4; j++) acc[mf][nf][j] = 0.f;

    int arow = (lane & 7) + ((lane >> 3) & 1) * 8;   // A ldmatrix row offset
    int acolo = (lane >> 4) * 8;                      // A ldmatrix col offset
    int bn = (lane & 7) + (lane >> 4) * 8;            // B ldmatrix n offset
    int bko = ((lane >> 3) & 1) * 8;                  // B ldmatrix k offset

    float pw0[16], pw1[16];
    for (int cc = 0; cc < 8; cc++) {
        // prefetch next W1 chunk into regs
        if (cc < 7) {
            #pragma unroll
            for (int rr = 0; rr < 16; rr++) {
                int g = wid * 16 + rr, nb = g >> 2, kb = g & 3;
                int n = nb * 8 + dn, kp = kb * 4 + kpv;
                int k0 = (cc + 1) * 32 + 2 * kp;
                pw0[rr] = __ldg(W1k + (size_t)k0 * TWO_E + n);
                pw1[rr] = __ldg(W1k + (size_t)(k0 + 1) * TWO_E + n);
            }
        }
        // compute on current buffer
        u32 bbase = sb + BS_O + (u32)(cc & 1) * BBUF;
        #pragma unroll
        for (int ks = 0; ks < 2; ks++) {
            u32 ah[2][4], al[2][4];
            int acol = cc * 32 + ks * 16 + acolo;
            #pragma unroll
            for (int mf = 0; mf < 2; mf++) {
                int row = wm * 32 + mf * 16 + arow;
                u32 ad = sb + AS_HI + row * 528 + acol * 2;
                LDMX4(ah[mf], ad);
                LDMX4(al[mf], ad + 33792);
            }
            u32 bh[8][2], bl[8][2];
            #pragma unroll
            for (int p = 0; p < 4; p++) {
                int n = wn * 64 + p * 16 + bn;
                u32 bd = bbase + n * 80 + (ks * 16 + bko) * 2;
                u32 t[4];
                LDMX4(t, bd);
                bh[2*p][0] = t[0]; bh[2*p][1] = t[1];
                bh[2*p+1][0] = t[2]; bh[2*p+1][1] = t[3];
                LDMX4(t, bd + 20480);
                bl[2*p][0] = t[0]; bl[2*p][1] = t[1];
                bl[2*p+1][0] = t[2]; bl[2*p+1][1] = t[3];
            }
            #pragma unroll
            for (int mf = 0; mf < 2; mf++)
                #pragma unroll
                for (int nf = 0; nf < 8; nf++) {
                    MMA_BF16(acc[mf][nf], ah[mf], bh[nf]);
                    MMA_BF16(acc[mf][nf], ah[mf], bl[nf]);
                    MMA_BF16(acc[mf][nf], al[mf], bh[nf]);
                }
        }
        // store prefetched chunk into the other buffer
        if (cc < 7) {
            char* buf = smem + BS_O + ((cc + 1) & 1) * BBUF;
            #pragma unroll
            for (int rr = 0; rr < 16; rr++) {
                int g = wid * 16 + rr, nb = g >> 2, kb = g & 3;
                int n = nb * 8 + dn, kp = kb * 4 + kpv;
                u32 hp, lp; split2(pw0[rr], pw1[rr], hp, lp);
                *(u32*)(buf + n * 80 + kp * 4) = hp;
                *(u32*)(buf + 20480 + n * 80 + kp * 4) = lp;
            }
        }
        __syncthreads();
    }

    // ---- epilogue1: bias+relu, split, H overwrites As ----------------------
    {
        int g4 = lane >> 2, c4 = lane & 3;
        #pragma unroll
        for (int mf = 0; mf < 2; mf++)
            #pragma unroll
            for (int nf = 0; nf < 8; nf++) {
                int col = wn * 64 + nf * 8 + 2 * c4;
                float2 bv = *(const float2*)(b1p + col);
                int row = wm * 32 + mf * 16 + g4;
                float v0 = fmaxf(acc[mf][nf][0] + bv.x, 0.f);
                float v1 = fmaxf(acc[mf][nf][1] + bv.y, 0.f);
                u32 hp, lp; split2(v0, v1, hp, lp);
                *(u32*)(smem + AS_HI + row * 528 + col * 2) = hp;
                *(u32*)(smem + AS_LO + row * 528 + col * 2) = lp;
                float v2 = fmaxf(acc[mf][nf][2] + bv.x, 0.f);
                float v3 = fmaxf(acc[mf][nf][3] + bv.y, 0.f);
                split2(v2, v3, hp, lp);
                *(u32*)(smem + AS_HI + (row + 8) * 528 + col * 2) = hp;
                *(u32*)(smem + AS_LO + (row + 8) * 528 + col * 2) = lp;
            }
    }

    // ---- stage W2 chunk 0 ---------------------------------------------------
    {
        char* buf = smem + BS_O;
        for (int rr = 0; rr < 8; rr++) {
            int g = wid * 8 + rr, nb = g >> 2, kb = g & 3;
            int n = nb * 8 + dn, kp = kb * 4 + kpv;
            float w0 = __ldg(W2k + (size_t)(2 * kp) * E + n);
            float w1 = __ldg(W2k + (size_t)(2 * kp + 1) * E + n);
            u32 hp, lp; split2(w0, w1, hp, lp);
            *(u32*)(buf + n * 80 + kp * 4) = hp;
            *(u32*)(buf + 20480 + n * 80 + kp * 4) = lp;
        }
    }
    __syncthreads();

    // =================== GEMM2: O[64,128] = H @ W2 =========================
    float a2[2][4][4];
    #pragma unroll
    for (int mf = 0; mf < 2; mf++)
        #pragma unroll
        for (int nf = 0; nf < 4; nf++)
            #pragma unroll
            for (int j = 0; j < 4; j++) a2[mf][nf][j] = 0.f;

    for (int cc = 0; cc < 8; cc++) {
        if (cc < 7) {
            #pragma unroll
            for (int rr = 0; rr < 8; rr++) {
                int g = wid * 8 + rr, nb = g >> 2, kb = g & 3;
                int n = nb * 8 + dn, kp = kb * 4 + kpv;
                int k0 = (cc + 1) * 32 + 2 * kp;
                pw0[rr] = __ldg(W2k + (size_t)k0 * E + n);
                pw1[rr] = __ldg(W2k + (size_t)(k0 + 1) * E + n);
            }
        }
        u32 bbase = sb + BS_O + (u32)(cc & 1) * BBUF;
        #pragma unroll
        for (int ks = 0; ks < 2; ks++) {
            u32 ah[2][4], al[2][4];
            int acol = cc * 32 + ks * 16 + acolo;
            #pragma unroll
            for (int mf = 0; mf < 2; mf++) {
                int row = wm * 32 + mf * 16 + arow;
                u32 ad = sb + AS_HI + row * 528 + acol * 2;
                LDMX4(ah[mf], ad);
                LDMX4(al[mf], ad + 33792);
            }
            u32 bh[4][2], bl[4][2];
            #pragma unroll
            for (int p = 0; p < 2; p++) {
                int n = wn * 32 + p * 16 + bn;
                u32 bd = bbase + n * 80 + (ks * 16 + bko) * 2;
                u32 t[4];
                LDMX4(t, bd);
                bh[2*p][0] = t[0]; bh[2*p][1] = t[1];
                bh[2*p+1][0] = t[2]; bh[2*p+1][1] = t[3];
                LDMX4(t, bd + 20480);
                bl[2*p][0] = t[0]; bl[2*p][1] = t[1];
                bl[2*p+1][0] = t[2]; bl[2*p+1][1] = t[3];
            }
            #pragma unroll
            for (int mf = 0; mf < 2; mf++)
                #pragma unroll
                for (int nf = 0; nf < 4; nf++) {
                    MMA_BF16(a2[mf][nf], ah[mf], bh[nf]);
                    MMA_BF16(a2[mf][nf], ah[mf], bl[nf]);
                    MMA_BF16(a2[mf][nf], al[mf], bh[nf]);
                }
        }
        if (cc < 7) {
            char* buf = smem + BS_O + ((cc + 1) & 1) * BBUF;
            #pragma unroll
            for (int rr = 0; rr < 8; rr++) {
                int g = wid * 8 + rr, nb = g >> 2, kb = g & 3;
                int n = nb * 8 + dn, kp = kb * 4 + kpv;
                u32 hp, lp; split2(pw0[rr], pw1[rr], hp, lp);
                *(u32*)(buf + n * 80 + kp * 4) = hp;
                *(u32*)(buf + 20480 + n * 80 + kp * 4) = lp;
            }
        }
        __syncthreads();
    }

    // ---- epilogue2: bias + store to gmem -----------------------------------
    {
        int g4 = lane >> 2, c4 = lane & 3;
        #pragma unroll
        for (int mf = 0; mf < 2; mf++)
            #pragma unroll
            for (int nf = 0; nf < 4; nf++) {
                int col = wn * 32 + nf * 8 + 2 * c4;
                float2 bv = *(const float2*)(b2p + col);
                int row = wm * 32 + mf * 16 + g4;
                int nd = s_node[row];
                if (nd >= 0) {
                    float2 o;
                    o.x = a2[mf][nf][0] + bv.x;
                    o.y = a2[mf][nf][1] + bv.y;
                    *(float2*)(outp + (size_t)nd * E + col) = o;
                }
                int nd2 = s_node[row + 8];
                if (nd2 >= 0) {
                    float2 o;
                    o.x = a2[mf][nf][2] + bv.x;
                    o.y = a2[mf][nf][3] + bv.y;
                    *(float2*)(outp + (size_t)nd2 * E + col) = o;
                }
            }
    }
}

// ---------------------------------------------------------------------------
// lf expert MLP: 256 -> relu(512) -> 128 (scalar packed-f32x2; ~3% of FLOPs)
// ---------------------------------------------------------------------------
__global__ void __launch_bounds__(256, 1)
lf_gemm_kernel(const float* __restrict__ W1, const float* __restrict__ b1,
               const float* __restrict__ W2, const float* __restrict__ b2) {
    extern __shared__ char smem[];
    float* Xt = (float*)(smem + LF_XT_OFF);
    float* Ht = (float*)(smem + LF_HT_OFF);
    float* Ws = (float*)(smem + LF_WS_OFF);
    int* s_node = (int*)(smem + LF_SN_OFF);

    int k_ex  = blockIdx.y;
    int count = g_counts[16 + k_ex];
    int m0    = blockIdx.x * TMLF;
    if (m0 >= count) return;
    int mrows = min(TMLF, count - m0);
    int tid   = threadIdx.x;

    if (tid < TMLF)
        s_node[tid] = (tid < mrows) ? g_lists[LBASE4 + k_ex * LFN + m0 + tid] : -1;
    __syncthreads();

    {
        int wid = tid >> 5, lane = tid & 31;
        #pragma unroll
        for (int i = 0; i < 4; i++) {
            int m = wid * 4 + i;
            int node = s_node[m];
            const float* src = 0;
            if (node >= 0) {
                int b = node / 9, g = node % 9;
                src = g_roots + ((size_t)b * Tt + 16 + 2 * g) * E;
            }
            #pragma unroll
            for (int j = 0; j < 8; j++) {
                int k = lane + 32 * j;
                Xt[k * XSTR + m] = src ? src[k] : 0.f;
            }
        }
    }

    int rg = tid & 7,  cg = tid >> 3;
    int r0 = rg * 4,   c0 = cg * 8;
    const float* W1k = W1 + (size_t)k_ex * TWO_E * 512;

    for (int pass = 0; pass < 2; pass++) {
        ull acc[4][4];
        #pragma unroll
        for (int i = 0; i < 4; i++)
            #pragma unroll
            for (int j = 0; j < 4; j++) acc[i][j] = 0ull;

        float4 pre[8];
        {
            #pragma unroll
            for (int i = 0; i < 8; i++) {
                int f = tid + i * 256, r = f >> 6, c4 = f & 63;
                pre[i] = __ldg((const float4*)W1k + (size_t)r * 128 + pass * 64 + c4);
            }
        }
        for (int cb = 0; cb < 8; cb++) {
            float4* Wsv = (float4*)Ws;
            #pragma unroll
            for (int i = 0; i < 8; i++) Wsv[tid + i * 256] = pre[i];
            __syncthreads();
            if (cb < 7) {
                #pragma unroll
                for (int i = 0; i < 8; i++) {
                    int f = tid + i * 256, r = f >> 6, c4 = f & 63;
                    pre[i] = __ldg((const float4*)W1k
                                   + (size_t)((cb + 1) * 32 + r) * 128 + pass * 64 + c4);
                }
            }
            #pragma unroll
            for (int kk = 0; kk < 32; kk++) {
                float4 x = *(const float4*)&Xt[(cb * 32 + kk) * XSTR + r0];
                ulonglong2 wa = *(const ulonglong2*)&Ws[kk * 256 + c0];
                ulonglong2 wb = *(const ulonglong2*)&Ws[kk * 256 + c0 + 4];
                ull xd[4] = {pack_dup(x.x), pack_dup(x.y), pack_dup(x.z), pack_dup(x.w)};
                #pragma unroll
                for (int i = 0; i < 4; i++) {
                    fma2(acc[i][0], xd[i], wa.x);
                    fma2(acc[i][1], xd[i], wa.y);
                    fma2(acc[i][2], xd[i], wb.x);
                    fma2(acc[i][3], xd[i], wb.y);
                }
            }
            __syncthreads();
        }
        int cabs = pass * 256 + c0;
        float4 bva = __ldg((const float4*)(b1 + k_ex * 512 + cabs));
        float4 bvb = __ldg((const float4*)(b1 + k_ex * 512 + cabs + 4));
        float bv[8] = {bva.x, bva.y, bva.z, bva.w, bvb.x, bvb.y, bvb.z, bvb.w};
        float a[4][8];
        #pragma unroll
        for (int i = 0; i < 4; i++)
            #pragma unroll
            for (int jp = 0; jp < 4; jp++) {
                float2 p = unpack2(acc[i][jp]);
                a[i][2 * jp]     = p.x;
                a[i][2 * jp + 1] = p.y;
            }
        #pragma unroll
        for (int j = 0; j < 8; j++) {
            float4 h;
            h.x = fmaxf(a[0][j] + bv[j], 0.f);
            h.y = fmaxf(a[1][j] + bv[j], 0.f);
            h.z = fmaxf(a[2][j] + bv[j], 0.f);
            h.w = fmaxf(a[3][j] + bv[j], 0.f);
            *(float4*)&Ht[(cabs + j) * XSTR + r0] = h;
        }
    }
    __syncthreads();

    int c2 = (tid >> 3) * 4;
    ull a2[4][2];
    #pragma unroll
    for (int i = 0; i < 4; i++) { a2[i][0] = 0ull; a2[i][1] = 0ull; }

    const float* W2k = W2 + (size_t)k_ex * 512 * E;
    float4 p2[4];
    {
        const float4* src = (const float4*)W2k;
        #pragma unroll
        for (int i = 0; i < 4; i++) p2[i] = __ldg(&src[tid + i * 256]);
    }
    for (int cb = 0; cb < 16; cb++) {
        float4* Wsv = (float4*)Ws;
        #pragma unroll
        for (int i = 0; i < 4; i++) Wsv[tid + i * 256] = p2[i];
        __syncthreads();
        if (cb < 15) {
            const float4* src = (const float4*)(W2k + (size_t)(cb + 1) * 32 * E);
            #pragma unroll
            for (int i = 0; i < 4; i++) p2[i] = __ldg(&src[tid + i * 256]);
        }
        #pragma unroll
        for (int kk = 0; kk < 32; kk++) {
            float4 h = *(const float4*)&Ht[(cb * 32 + kk) * XSTR + r0];
            ulonglong2 w = *(const ulonglong2*)&Ws[kk * E + c2];
            ull hd[4] = {pack_dup(h.x), pack_dup(h.y), pack_dup(h.z), pack_dup(h.w)};
            #pragma unroll
            for (int i = 0; i < 4; i++) {
                fma2(a2[i][0], hd[i], w.x);
                fma2(a2[i][1], hd[i], w.y);
            }
        }
        __syncthreads();
    }
    {
        float4 bv = __ldg((const float4*)(b2 + k_ex * E + c2));
        #pragma unroll
        for (int i = 0; i < 4; i++) {
            int node = s_node[r0 + i];
            if (node >= 0) {
                float2 pa = unpack2(a2[i][0]);
                float2 pb = unpack2(a2[i][1]);
                float4 o;
                o.x = pa.x + bv.x; o.y = pa.y + bv.y;
                o.z = pb.x + bv.z; o.w = pb.y + bv.w;
                *(float4*)(g_stmt + (size_t)node * E + c2) = o;
            }
        }
    }
}

// ---------------------------------------------------------------------------
// Attention tail (unchanged)
// ---------------------------------------------------------------------------
__global__ void attn_kernel(const int* __restrict__ th_idx,
                            const float* __restrict__ th_emb,
                            const float* __restrict__ he_W, const float* __restrict__ he_b,
                            const float* __restrict__ hg_W, const float* __restrict__ hg_b,
                            const float* __restrict__ ht_W, const float* __restrict__ ht_b,
                            float* __restrict__ out) {
    __shared__ float obj[E];
    __shared__ float q[E];
    __shared__ float keys[16][E + 1];
    __shared__ float a[16];
    int b = blockIdx.x, tid = threadIdx.x;

    float o = g_stmt[((size_t)b * 9 + 8) * E + tid];
    obj[tid] = o;
    out[(size_t)b * 512 + tid] = o;
    __syncthreads();

    for (int t3 = 0; t3 < 3; t3++) {
        int n; const float *W, *bb;
        if (t3 == 0) {
            n = 8; W = hg_W; bb = hg_b;
            for (int i = 0; i < 8; i++)
                keys[i][tid] = g_stmt[((size_t)b * 9 + i) * E + tid];
        } else if (t3 == 1) {
            n = 16; W = he_W; bb = he_b;
            for (int i = 0; i < 16; i++)
                keys[i][tid] = g_roots[((size_t)b * Tt + i) * E + tid];
        } else {
            n = 8; W = ht_W; bb = ht_b;
            for (int i = 0; i < 8; i++)
                keys[i][tid] = th_emb[(size_t)th_idx[b * 8 + i] * E + tid];
        }
        float qv = bb[tid];
        for (int k = 0; k < E; k++) qv = fmaf(obj[k], W[k * E + tid], qv);
        q[tid] = qv;
        __syncthreads();
        if (tid < n) {
            float s = 0.f;
            for (int d = 0; d < E; d++) s = fmaf(keys[tid][d], q[d], s);
            a[tid] = s;
        }
        __syncthreads();
        if (tid == 0) {
            float mx = -1e30f;
            for (int i = 0; i < n; i++) mx = fmaxf(mx, a[i]);
            float sum = 0.f;
            for (int i = 0; i < n; i++) { float e = expf(a[i] - mx); a[i] = e; sum += e; }
            float inv = 1.f / sum;
            for (int i = 0; i < n; i++) a[i] *= inv;
        }
        __syncthreads();
        float c = 0.f;
        for (int i = 0; i < n; i++) c = fmaf(a[i], keys[i][tid], c);
        int off = (t3 == 0) ? 128 : (t3 == 1) ? 256 : 384;
        out[(size_t)b * 512 + off + tid] = c;
        __syncthreads();
    }
}

// ---------------------------------------------------------------------------
extern "C" void kernel_launch(void* const* d_in, const int* in_sizes, int n_in,
                              void* d_out, int out_size) {
    const int*   leaf_idx = (const int*)d_in[0];
    const int*   nf_ids   = (const int*)d_in[1];
    const int*   lf_ids   = (const int*)d_in[2];
    const int*   th_idx   = (const int*)d_in[3];
    const float* ent_emb  = (const float*)d_in[4];
    const float* th_emb   = (const float*)d_in[5];
    const float* nf_W1 = (const float*)d_in[6];
    const float* nf_b1 = (const float*)d_in[7];
    const float* nf_W2 = (const float*)d_in[8];
    const float* nf_b2 = (const float*)d_in[9];
    const float* lf_W1 = (const float*)d_in[10];
    const float* lf_b1 = (const float*)d_in[11];
    const float* lf_W2 = (const float*)d_in[12];
    const float* lf_b2 = (const float*)d_in[13];
    const float* he_W = (const float*)d_in[14];
    const float* he_b = (const float*)d_in[15];
    const float* hg_W = (const float*)d_in[16];
    const float* hg_b = (const float*)d_in[17];
    const float* ht_W = (const float*)d_in[18];
    const float* ht_b = (const float*)d_in[19];
    float* out = (float*)d_out;

    cudaFuncSetAttribute(nf_mma_kernel, cudaFuncAttributeMaxDynamicSharedMemorySize, NF_SMEM);
    cudaFuncSetAttribute(lf_gemm_kernel, cudaFuncAttributeMaxDynamicSharedMemorySize, LF_SMEM);

    zero_counts_kernel<<<1, 32>>>();
    compact_kernel<<<(L0N + L1N + L2N + L3N + LFN) / 256, 256>>>(nf_ids, lf_ids);

    nf_mma_kernel<<<dim3(L0N / 64, 4), 256, NF_SMEM>>>(0, leaf_idx, ent_emb,
        nf_W1, nf_b1, nf_W2, nf_b2);
    nf_mma_kernel<<<dim3(L1N / 64, 4), 256, NF_SMEM>>>(1, leaf_idx, ent_emb,
        nf_W1, nf_b1, nf_W2, nf_b2);
    nf_mma_kernel<<<dim3(L2N / 64, 4), 256, NF_SMEM>>>(2, leaf_idx, ent_emb,
        nf_W1, nf_b1, nf_W2, nf_b2);
    nf_mma_kernel<<<dim3(L3N / 64, 4), 256, NF_SMEM>>>(3, leaf_idx, ent_emb,
        nf_W1, nf_b1, nf_W2, nf_b2);

    lf_gemm_kernel<<<dim3(LFN / TMLF, 3), 256, LF_SMEM>>>(lf_W1, lf_b1, lf_W2, lf_b2);

    attn_kernel<<<Bn, E>>>(th_idx, th_emb, he_W, he_b, hg_W, hg_b, ht_W, ht_b, out);
}